// round 5
// baseline (speedup 1.0000x reference)
#include <cuda_runtime.h>
#include <cuda_fp16.h>
#include <cstdint>

#define NN 100000
#define EE 1600000
#define DD 128
#define CC 100
#define CAP (EE + 8 * NN)     // padded CSR capacity
#define ROW16 (DD / 8)        // int4 chunks per fp16 row (16)

// ---------------- scratch (static device globals; no runtime allocation) ----
__device__ int   g_mask_mode;            // 0=int32, 1=float32, 2=bytes
__device__ int   g_deg[NN];
__device__ int   g_off[NN];
__device__ int   g_cur[NN];
__device__ float g_dis[NN];              // deg^{-1/2} (0 if deg==0)
__device__ int   g_counter;
__device__ __align__(16) int2 g_csr [CAP];  // (src, bits(alpha*norm)), dst-grouped, 8-padded
__device__ __align__(16) int2 g_csrL[CAP];  // (labelOrCC, bits(alpha*norm)) for layer 1
__device__ __align__(16) int4 g_protoH[(CC + 1) * ROW16]; // fp16 protos + zero row
__device__ __align__(128) __half g_H1[(size_t)NN * DD];
__device__ __align__(128) __half g_H2[(size_t)NN * DD];

// ---------------- mask dtype detection -------------------------------------
__global__ void k_detect(const unsigned int* m) {
    __shared__ int s_gt1, s_nf;
    if (threadIdx.x == 0) { s_gt1 = 0; s_nf = 0; }
    __syncthreads();
    int gt1 = 0, nf = 0;
    for (int i = threadIdx.x; i < NN / 4; i += blockDim.x) {
        unsigned w = m[i];
        if (w > 1u) gt1 = 1;
        if (w != 0u && w != 0x3F800000u) nf = 1;
    }
    if (gt1) atomicOr(&s_gt1, 1);
    if (nf)  atomicOr(&s_nf, 1);
    __syncthreads();
    if (threadIdx.x == 0)
        g_mask_mode = (!s_gt1) ? 0 : ((!s_nf) ? 1 : 2);
}

__device__ __forceinline__ int read_mask(const void* m, int n) {
    int mode = g_mask_mode;
    if (mode == 0) return ((const int*)m)[n] != 0;
    if (mode == 1) return ((const float*)m)[n] != 0.0f;
    return ((const unsigned char*)m)[n] != 0;
}

// ---------------- proto conversion: fp32 -> fp16 (+ zero row CC) -------------
__global__ void k_protoh(const float4* __restrict__ protos4) {
    int t = blockIdx.x * blockDim.x + threadIdx.x;
    if (t >= (CC + 1) * ROW16) return;
    int row = t >> 4, c = t & 15;
    int4 o = make_int4(0, 0, 0, 0);
    if (row < CC) {
        float4 a = protos4[(size_t)row * 32 + 2 * c];
        float4 b = protos4[(size_t)row * 32 + 2 * c + 1];
        __half2 h0 = __floats2half2_rn(a.x, a.y);
        __half2 h1 = __floats2half2_rn(a.z, a.w);
        __half2 h2 = __floats2half2_rn(b.x, b.y);
        __half2 h3 = __floats2half2_rn(b.z, b.w);
        o.x = *reinterpret_cast<int*>(&h0); o.y = *reinterpret_cast<int*>(&h1);
        o.z = *reinterpret_cast<int*>(&h2); o.w = *reinterpret_cast<int*>(&h3);
    }
    g_protoH[t] = o;
}

// ---------------- CSR build --------------------------------------------------
__global__ void k_zero() {
    int i = blockIdx.x * blockDim.x + threadIdx.x;
    if (i < NN) g_deg[i] = 0;
    if (i == 0) g_counter = 0;
}

__global__ void k_deg(const int* __restrict__ dst) {
    int e = blockIdx.x * blockDim.x + threadIdx.x;
    if (e < EE) atomicAdd(&g_deg[dst[e]], 1);
}

// dis + disjoint contiguous 8-padded range per node + pad tail with dummies
__global__ void k_dis_off() {
    int i = blockIdx.x * blockDim.x + threadIdx.x;
    if (i < NN) {
        int d = g_deg[i];
        g_dis[i] = (d > 0) ? rsqrtf((float)d) : 0.0f;
        int dp = (d + 7) & ~7;
        int o = atomicAdd(&g_counter, dp);
        g_off[i] = o;
        g_cur[i] = o;
        for (int p = o + d; p < o + dp; p++) {
            g_csr[p]  = make_int2(0, 0);      // src 0, weight 0
            g_csrL[p] = make_int2(CC, 0);     // zero proto row, weight 0
        }
    }
}

__global__ void k_fill(const int* __restrict__ src, const int* __restrict__ dst,
                       const int* __restrict__ labels, const void* __restrict__ mask,
                       const float* __restrict__ alpha) {
    int e = blockIdx.x * blockDim.x + threadIdx.x;
    if (e >= EE) return;
    int s = src[e], d = dst[e];
    float nw = alpha[0] * g_dis[s] * g_dis[d];
    int p = atomicAdd(&g_cur[d], 1);
    int nb = __float_as_int(nw);
    g_csr[p]  = make_int2(s, nb);
    g_csrL[p] = make_int2(read_mask(mask, s) ? labels[s] : CC, nb);
}

// ---------------- helpers ----------------------------------------------------
__device__ __forceinline__ float clamp01(float x) {
    return fminf(fmaxf(x, 0.f), 1.f);
}

__device__ __forceinline__ void accum8(float acc[8], int4 v, float nw) {
    float2 f0 = __half22float2(*reinterpret_cast<__half2*>(&v.x));
    float2 f1 = __half22float2(*reinterpret_cast<__half2*>(&v.y));
    float2 f2 = __half22float2(*reinterpret_cast<__half2*>(&v.z));
    float2 f3 = __half22float2(*reinterpret_cast<__half2*>(&v.w));
    acc[0] += nw * f0.x; acc[1] += nw * f0.y;
    acc[2] += nw * f1.x; acc[3] += nw * f1.y;
    acc[4] += nw * f2.x; acc[5] += nw * f2.y;
    acc[6] += nw * f3.x; acc[7] += nw * f3.y;
}

// Pair-gather core: half-warp 0 handles even edges, half-warp 1 odd edges.
// Each lane covers one 16B chunk of the fp16 row; combine via shfl_xor(16).
__device__ __forceinline__ void gcore(int w, int lane,
                                      const int4* __restrict__ inH,
                                      const int2* __restrict__ csr,
                                      float acc[8]) {
    int off = g_off[w];
    int degP = (g_deg[w] + 7) & ~7;
    const int4* cp = (const int4*)(csr + off);   // 16B aligned (off multiple of 8)
    int half = lane >> 4;
    int chunk = lane & 15;
    for (int base = 0; base < degP; base += 8) {
        int4 c0 = cp[base / 2 + 0];   // entries 0,1 : (s0,n0,s1,n1)
        int4 c1 = cp[base / 2 + 1];
        int4 c2 = cp[base / 2 + 2];
        int4 c3 = cp[base / 2 + 3];
        int s0, s1, s2, s3; float n0, n1, n2, n3;
        if (half == 0) {
            s0 = c0.x; n0 = __int_as_float(c0.y);
            s1 = c1.x; n1 = __int_as_float(c1.y);
            s2 = c2.x; n2 = __int_as_float(c2.y);
            s3 = c3.x; n3 = __int_as_float(c3.y);
        } else {
            s0 = c0.z; n0 = __int_as_float(c0.w);
            s1 = c1.z; n1 = __int_as_float(c1.w);
            s2 = c2.z; n2 = __int_as_float(c2.w);
            s3 = c3.z; n3 = __int_as_float(c3.w);
        }
        int4 v0 = inH[(size_t)s0 * ROW16 + chunk];
        int4 v1 = inH[(size_t)s1 * ROW16 + chunk];
        int4 v2 = inH[(size_t)s2 * ROW16 + chunk];
        int4 v3 = inH[(size_t)s3 * ROW16 + chunk];
        accum8(acc, v0, n0);
        accum8(acc, v1, n1);
        accum8(acc, v2, n2);
        accum8(acc, v3, n3);
    }
    #pragma unroll
    for (int k = 0; k < 8; k++)
        acc[k] += __shfl_xor_sync(0xffffffffu, acc[k], 16);
}

// residual float4 for this lane's quarter-chunk: protos4 index 2*chunk + half
__device__ __forceinline__ float4 lane_out(int w, int lane, const float acc[8],
                                           const float4* __restrict__ protos4,
                                           const int* __restrict__ labels,
                                           const void* __restrict__ mask,
                                           float rc) {
    int half = lane >> 4, chunk = lane & 15;
    float4 r = make_float4(0.f, 0.f, 0.f, 0.f);
    if (read_mask(mask, w)) {
        float4 p = protos4[(size_t)labels[w] * 32 + 2 * chunk + half];
        r.x = rc * p.x; r.y = rc * p.y; r.z = rc * p.z; r.w = rc * p.w;
    }
    int b = half * 4;
    float4 o;
    o.x = clamp01(acc[b + 0] + r.x);
    o.y = clamp01(acc[b + 1] + r.y);
    o.z = clamp01(acc[b + 2] + r.z);
    o.w = clamp01(acc[b + 3] + r.w);
    return o;
}

// ---------------- gather, fp16 output ---------------------------------------
__global__ void k_gather_h(uint2* __restrict__ outH2,
                           const int4* __restrict__ inH,
                           const int2* __restrict__ csr,
                           const float4* __restrict__ protos4,
                           const int* __restrict__ labels,
                           const void* __restrict__ mask,
                           const float* __restrict__ alpha) {
    int w = (blockIdx.x * blockDim.x + threadIdx.x) >> 5;
    int lane = threadIdx.x & 31;
    if (w >= NN) return;
    float acc[8] = {0.f, 0.f, 0.f, 0.f, 0.f, 0.f, 0.f, 0.f};
    gcore(w, lane, inH, csr, acc);
    float4 o = lane_out(w, lane, acc, protos4, labels, mask, 1.0f - alpha[0]);
    __half2 ha = __floats2half2_rn(o.x, o.y);
    __half2 hb = __floats2half2_rn(o.z, o.w);
    uint2 u;
    u.x = *reinterpret_cast<unsigned int*>(&ha);
    u.y = *reinterpret_cast<unsigned int*>(&hb);
    int half = lane >> 4, chunk = lane & 15;
    outH2[(size_t)w * 32 + 2 * chunk + half] = u;
}

// ---------------- gather, fp32 output (final layer) --------------------------
__global__ void k_gather_f(float4* __restrict__ out4,
                           const int4* __restrict__ inH,
                           const int2* __restrict__ csr,
                           const float4* __restrict__ protos4,
                           const int* __restrict__ labels,
                           const void* __restrict__ mask,
                           const float* __restrict__ alpha) {
    int w = (blockIdx.x * blockDim.x + threadIdx.x) >> 5;
    int lane = threadIdx.x & 31;
    if (w >= NN) return;
    float acc[8] = {0.f, 0.f, 0.f, 0.f, 0.f, 0.f, 0.f, 0.f};
    gcore(w, lane, inH, csr, acc);
    float4 o = lane_out(w, lane, acc, protos4, labels, mask, 1.0f - alpha[0]);
    int half = lane >> 4, chunk = lane & 15;
    out4[(size_t)w * 32 + 2 * chunk + half] = o;
}

// ---------------- launch -----------------------------------------------------
extern "C" void kernel_launch(void* const* d_in, const int* in_sizes, int n_in,
                              void* d_out, int out_size) {
    const void*  mask   = d_in[0];                       // bool [N]
    const float* protos = (const float*)d_in[1];         // [C, D]
    const int*   labels = (const int*)d_in[2];           // [N]
    const int*   ei     = (const int*)d_in[3];           // [2, E]
    const float* alpha  = (const float*)d_in[4];         // scalar
    const int* src = ei;
    const int* dst = ei + EE;
    const float4* protos4 = (const float4*)protos;

    __half* H1; cudaGetSymbolAddress((void**)&H1, g_H1);
    __half* H2; cudaGetSymbolAddress((void**)&H2, g_H2);
    int2* csr;  cudaGetSymbolAddress((void**)&csr,  g_csr);
    int2* csrL; cudaGetSymbolAddress((void**)&csrL, g_csrL);
    int4* protoH; cudaGetSymbolAddress((void**)&protoH, g_protoH);

    const int TB = 256;
    const int nodeBlocks = (NN + TB - 1) / TB;
    const int edgeBlocks = (EE + TB - 1) / TB;
    const int warpBlocks = (NN * 32 + TB - 1) / TB;   // warp per node
    const int protoBlocks = ((CC + 1) * ROW16 + TB - 1) / TB;

    k_detect<<<1, 1024>>>((const unsigned int*)mask);
    k_zero<<<nodeBlocks, TB>>>();
    k_protoh<<<protoBlocks, TB>>>(protos4);
    k_deg<<<edgeBlocks, TB>>>(dst);
    k_dis_off<<<nodeBlocks, TB>>>();
    k_fill<<<edgeBlocks, TB>>>(src, dst, labels, mask, alpha);

    // layer 1: gather fp16 protos via label-CSR
    k_gather_h<<<warpBlocks, TB>>>((uint2*)H1, (const int4*)protoH, csrL,
                                   protos4, labels, mask, alpha);
    // layer 2: H1 -> H2
    k_gather_h<<<warpBlocks, TB>>>((uint2*)H2, (const int4*)H1, csr,
                                   protos4, labels, mask, alpha);
    // layer 3: H2 -> fp32 out
    k_gather_f<<<warpBlocks, TB>>>((float4*)d_out, (const int4*)H2, csr,
                                   protos4, labels, mask, alpha);
}

// round 6
// speedup vs baseline: 1.0968x; 1.0968x over previous
#include <cuda_runtime.h>
#include <cuda_fp16.h>
#include <cstdint>

#define NN 100000
#define EE 1600000
#define DD 128
#define CC 100
#define CAP (EE + 8 * NN)     // padded CSR capacity
#define ROW16 (DD / 8)        // int4 chunks per fp16 row (16)

// ---------------- scratch (static device globals; no runtime allocation) ----
__device__ int   g_flag_gt1, g_flag_nf;  // mask dtype flags
__device__ int   g_deg[NN];
__device__ int   g_off[NN];
__device__ int   g_cur[NN];
__device__ float g_dis[NN];              // deg^{-1/2} (0 if deg==0)
__device__ int   g_nodeLab[NN];          // label if masked else CC
__device__ int   g_counter;
__device__ __align__(16) int2 g_csr[CAP];   // (src, bits(alpha*norm)), dst-grouped, 8-padded
__device__ __align__(16) int4 g_protoH[(CC + 1) * ROW16]; // fp16 protos + zero row CC
__device__ __align__(128) __half g_H1[(size_t)NN * DD];
__device__ __align__(128) __half g_H2[(size_t)NN * DD];

// ---------------- mask dtype detection (flags) ------------------------------
//  int32 0/1  -> words all in {0,1}            : gt1=0
//  float 0/1  -> words all in {0,0x3F800000}   : gt1=1, nf=0
//  bytes 0/1  -> packed bools                  : gt1=1, nf=1   (w.h.p.)
__device__ __forceinline__ int read_mask(const void* m, int n) {
    if (!g_flag_gt1) return ((const int*)m)[n] != 0;
    if (!g_flag_nf)  return ((const float*)m)[n] != 0.0f;
    return ((const unsigned char*)m)[n] != 0;
}

__global__ void k_detect(const unsigned int* __restrict__ m) {
    __shared__ int s_gt1, s_nf;
    if (threadIdx.x == 0) { s_gt1 = 0; s_nf = 0; }
    __syncthreads();
    int gt1 = 0, nf = 0;
    for (int i = blockIdx.x * blockDim.x + threadIdx.x; i < NN / 4;
         i += gridDim.x * blockDim.x) {
        unsigned w = m[i];
        if (w > 1u) gt1 = 1;
        if (w != 0u && w != 0x3F800000u) nf = 1;
    }
    if (gt1) atomicOr(&s_gt1, 1);
    if (nf)  atomicOr(&s_nf, 1);
    __syncthreads();
    if (threadIdx.x == 0) {
        if (s_gt1) atomicOr(&g_flag_gt1, 1);
        if (s_nf)  atomicOr(&g_flag_nf, 1);
    }
}

// ---------------- proto conversion: fp32 -> fp16 (+ zero row CC) -------------
__global__ void k_protoh(const float4* __restrict__ protos4) {
    int t = blockIdx.x * blockDim.x + threadIdx.x;
    if (t >= (CC + 1) * ROW16) return;
    int row = t >> 4, c = t & 15;
    int4 o = make_int4(0, 0, 0, 0);
    if (row < CC) {
        float4 a = protos4[(size_t)row * 32 + 2 * c];
        float4 b = protos4[(size_t)row * 32 + 2 * c + 1];
        __half2 h0 = __floats2half2_rn(a.x, a.y);
        __half2 h1 = __floats2half2_rn(a.z, a.w);
        __half2 h2 = __floats2half2_rn(b.x, b.y);
        __half2 h3 = __floats2half2_rn(b.z, b.w);
        o.x = *reinterpret_cast<int*>(&h0); o.y = *reinterpret_cast<int*>(&h1);
        o.z = *reinterpret_cast<int*>(&h2); o.w = *reinterpret_cast<int*>(&h3);
    }
    g_protoH[t] = o;
}

// ---------------- CSR build --------------------------------------------------
__global__ void k_zero() {
    int i = blockIdx.x * blockDim.x + threadIdx.x;
    if (i < NN) g_deg[i] = 0;
    if (i == 0) { g_counter = 0; g_flag_gt1 = 0; g_flag_nf = 0; }
}

// 4 edges per thread via int4
__global__ void k_deg(const int4* __restrict__ dst4) {
    int t = blockIdx.x * blockDim.x + threadIdx.x;
    if (t >= EE / 4) return;
    int4 d = dst4[t];
    atomicAdd(&g_deg[d.x], 1);
    atomicAdd(&g_deg[d.y], 1);
    atomicAdd(&g_deg[d.z], 1);
    atomicAdd(&g_deg[d.w], 1);
}

// dis + 8-padded disjoint range + dummy-pad tail + nodeLab
__global__ void k_dis_off(const int* __restrict__ labels, const void* __restrict__ mask) {
    int i = blockIdx.x * blockDim.x + threadIdx.x;
    if (i >= NN) return;
    int d = g_deg[i];
    g_dis[i] = (d > 0) ? rsqrtf((float)d) : 0.0f;
    g_nodeLab[i] = read_mask(mask, i) ? labels[i] : CC;
    int dp = (d + 7) & ~7;
    int o = atomicAdd(&g_counter, dp);
    g_off[i] = o;
    g_cur[i] = o;
    for (int p = o + d; p < o + dp; p++)
        g_csr[p] = make_int2(0, 0);          // src 0, weight 0
}

__global__ void k_fill(const int* __restrict__ src, const int* __restrict__ dst,
                       const float* __restrict__ alpha) {
    int e = blockIdx.x * blockDim.x + threadIdx.x;
    if (e >= EE) return;
    int s = src[e], d = dst[e];
    float nw = alpha[0] * g_dis[s] * g_dis[d];
    int p = atomicAdd(&g_cur[d], 1);
    g_csr[p] = make_int2(s, __float_as_int(nw));
}

// ---------------- helpers ----------------------------------------------------
__device__ __forceinline__ float clamp01(float x) {
    return fminf(fmaxf(x, 0.f), 1.f);
}

__device__ __forceinline__ void accum4(float4& acc, uint2 u, float nw) {
    float2 fa = __half22float2(*reinterpret_cast<__half2*>(&u.x));
    float2 fb = __half22float2(*reinterpret_cast<__half2*>(&u.y));
    acc.x += nw * fa.x; acc.y += nw * fa.y;
    acc.z += nw * fb.x; acc.w += nw * fb.y;
}

// Full-warp gather core (R4 style): lane covers one uint2 (4 halfs) of the row.
// USELAB: indirect src through g_nodeLab (layer 1, rows come from g_protoH).
template <bool USELAB>
__device__ __forceinline__ float4 gcore(int w, int lane,
                                        const uint2* __restrict__ in) {
    int off = g_off[w];
    int degP = (g_deg[w] + 7) & ~7;
    const int4* cp = (const int4*)(g_csr + off);   // 16B aligned (off multiple of 8)
    const uint2* inl = in + lane;
    float4 acc = make_float4(0.f, 0.f, 0.f, 0.f);
    for (int base = 0; base < degP; base += 8) {
        int4 c01 = cp[base / 2 + 0];
        int4 c23 = cp[base / 2 + 1];
        int4 c45 = cp[base / 2 + 2];
        int4 c67 = cp[base / 2 + 3];
        int   sr[8] = { c01.x, c01.z, c23.x, c23.z, c45.x, c45.z, c67.x, c67.z };
        float nw[8] = { __int_as_float(c01.y), __int_as_float(c01.w),
                        __int_as_float(c23.y), __int_as_float(c23.w),
                        __int_as_float(c45.y), __int_as_float(c45.w),
                        __int_as_float(c67.y), __int_as_float(c67.w) };
        if (USELAB) {
            #pragma unroll
            for (int j = 0; j < 8; j++) sr[j] = g_nodeLab[sr[j]];
        }
        uint2 v[8];
        #pragma unroll
        for (int j = 0; j < 8; j++)
            v[j] = inl[(size_t)sr[j] * 32];
        #pragma unroll
        for (int j = 0; j < 8; j++)
            accum4(acc, v[j], nw[j]);
    }
    return acc;
}

// residual + clamp for this lane's 4 features (fp32 protos for exact residual)
__device__ __forceinline__ float4 lane_out(int w, int lane, float4 acc,
                                           const float4* __restrict__ protos4,
                                           const int* __restrict__ labels,
                                           const void* __restrict__ mask,
                                           float rc) {
    float4 r = make_float4(0.f, 0.f, 0.f, 0.f);
    if (read_mask(mask, w)) {
        float4 p = protos4[(size_t)labels[w] * 32 + lane];
        r.x = rc * p.x; r.y = rc * p.y; r.z = rc * p.z; r.w = rc * p.w;
    }
    float4 o;
    o.x = clamp01(acc.x + r.x); o.y = clamp01(acc.y + r.y);
    o.z = clamp01(acc.z + r.z); o.w = clamp01(acc.w + r.w);
    return o;
}

__device__ __forceinline__ uint2 pack_half4(float4 o) {
    __half2 a = __floats2half2_rn(o.x, o.y);
    __half2 b = __floats2half2_rn(o.z, o.w);
    uint2 u;
    u.x = *reinterpret_cast<unsigned int*>(&a);
    u.y = *reinterpret_cast<unsigned int*>(&b);
    return u;
}

// ---------------- gather kernels ---------------------------------------------
template <bool USELAB>
__global__ void k_gather_h(uint2* __restrict__ out,
                           const uint2* __restrict__ in,
                           const float4* __restrict__ protos4,
                           const int* __restrict__ labels,
                           const void* __restrict__ mask,
                           const float* __restrict__ alpha) {
    int w = (blockIdx.x * blockDim.x + threadIdx.x) >> 5;
    int lane = threadIdx.x & 31;
    if (w >= NN) return;
    float4 acc = gcore<USELAB>(w, lane, in);
    float4 o = lane_out(w, lane, acc, protos4, labels, mask, 1.0f - alpha[0]);
    out[(size_t)w * 32 + lane] = pack_half4(o);
}

__global__ void k_gather_f(float4* __restrict__ out,
                           const uint2* __restrict__ in,
                           const float4* __restrict__ protos4,
                           const int* __restrict__ labels,
                           const void* __restrict__ mask,
                           const float* __restrict__ alpha) {
    int w = (blockIdx.x * blockDim.x + threadIdx.x) >> 5;
    int lane = threadIdx.x & 31;
    if (w >= NN) return;
    float4 acc = gcore<false>(w, lane, in);
    out[(size_t)w * 32 + lane] =
        lane_out(w, lane, acc, protos4, labels, mask, 1.0f - alpha[0]);
}

// ---------------- launch -----------------------------------------------------
extern "C" void kernel_launch(void* const* d_in, const int* in_sizes, int n_in,
                              void* d_out, int out_size) {
    const void*  mask   = d_in[0];                       // bool [N]
    const float* protos = (const float*)d_in[1];         // [C, D]
    const int*   labels = (const int*)d_in[2];           // [N]
    const int*   ei     = (const int*)d_in[3];           // [2, E]
    const float* alpha  = (const float*)d_in[4];         // scalar
    const int* src = ei;
    const int* dst = ei + EE;
    const float4* protos4 = (const float4*)protos;

    __half* H1; cudaGetSymbolAddress((void**)&H1, g_H1);
    __half* H2; cudaGetSymbolAddress((void**)&H2, g_H2);
    int4* protoH; cudaGetSymbolAddress((void**)&protoH, g_protoH);

    const int TB = 256;
    const int nodeBlocks  = (NN + TB - 1) / TB;
    const int edgeBlocks  = (EE + TB - 1) / TB;
    const int deg4Blocks  = (EE / 4 + TB - 1) / TB;
    const int warpBlocks  = (NN * 32 + TB - 1) / TB;   // warp per node
    const int protoBlocks = ((CC + 1) * ROW16 + TB - 1) / TB;

    k_zero<<<nodeBlocks, TB>>>();
    k_detect<<<64, TB>>>((const unsigned int*)mask);
    k_protoh<<<protoBlocks, TB>>>(protos4);
    k_deg<<<deg4Blocks, TB>>>((const int4*)dst);
    k_dis_off<<<nodeBlocks, TB>>>(labels, mask);
    k_fill<<<edgeBlocks, TB>>>(src, dst, alpha);

    // layer 1: rows from fp16 protos via nodeLab indirection
    k_gather_h<true><<<warpBlocks, TB>>>((uint2*)H1, (const uint2*)protoH,
                                         protos4, labels, mask, alpha);
    // layer 2: H1 -> H2
    k_gather_h<false><<<warpBlocks, TB>>>((uint2*)H2, (const uint2*)H1,
                                          protos4, labels, mask, alpha);
    // layer 3: H2 -> fp32 out
    k_gather_f<<<warpBlocks, TB>>>((float4*)d_out, (const uint2*)H2,
                                   protos4, labels, mask, alpha);
}